// round 1
// baseline (speedup 1.0000x reference)
#include <cuda_runtime.h>
#include <cstdint>
#include <math.h>

#define N_ITEMS 8192
#define DIM     64
#define BATCHSZ 4096
#define INV_T   14.2857142857142857f   /* 1/0.07 */

// ---------------- device scratch (no allocations allowed) ----------------
__device__ float  g_feat[N_ITEMS * DIM];                 // normalized, [row][k]
__device__ double g_featd[(size_t)DIM * N_ITEMS];        // [k][j], each f32 splatted to f32x2
__device__ float  g_partial[128];

// ---------------- f32x2 helpers (packed fp32 pair in one 64-bit reg) -----
static __device__ __forceinline__ unsigned long long fma2(unsigned long long a,
                                                          unsigned long long b,
                                                          unsigned long long c) {
    unsigned long long d;
    asm("fma.rn.f32x2 %0, %1, %2, %3;" : "=l"(d) : "l"(a), "l"(b), "l"(c));
    return d;
}
static __device__ __forceinline__ unsigned long long pack2(float lo, float hi) {
    unsigned long long d;
    asm("mov.b64 %0, {%1, %2};" : "=l"(d) : "f"(lo), "f"(hi));
    return d;
}
static __device__ __forceinline__ void unpack2(unsigned long long d, float& lo, float& hi) {
    asm("mov.b64 {%0, %1}, %2;" : "=f"(lo), "=f"(hi) : "l"(d));
}

// ---------------- kernel 1: row-normalize emb, build splatted transpose ---
__global__ __launch_bounds__(256) void normalize_kernel(const float* __restrict__ emb) {
    int warp = (blockIdx.x * blockDim.x + threadIdx.x) >> 5;
    int lane = threadIdx.x & 31;
    if (warp >= N_ITEMS) return;
    float2 v = reinterpret_cast<const float2*>(emb + (size_t)warp * DIM)[lane];
    float ss = v.x * v.x + v.y * v.y;
    #pragma unroll
    for (int o = 16; o; o >>= 1) ss += __shfl_xor_sync(0xFFFFFFFFu, ss, o);
    float inv = 1.0f / fmaxf(sqrtf(ss), 1e-12f);
    float a = v.x * inv, b = v.y * inv;
    g_feat[warp * DIM + 2 * lane]     = a;
    g_feat[warp * DIM + 2 * lane + 1] = b;
    g_featd[(size_t)(2 * lane)     * N_ITEMS + warp] = __longlong_as_double((long long)pack2(a, a));
    g_featd[(size_t)(2 * lane + 1) * N_ITEMS + warp] = __longlong_as_double((long long)pack2(b, b));
}

// ---------------- kernel 2: rating = sigmoid(emb[idx] @ w + b) ------------
__global__ __launch_bounds__(256) void rating_kernel(const int* __restrict__ idx,
                                                     const float* __restrict__ emb,
                                                     const float* __restrict__ w,
                                                     const float* __restrict__ bias,
                                                     float* __restrict__ out) {
    int warp = (blockIdx.x * blockDim.x + threadIdx.x) >> 5;
    int lane = threadIdx.x & 31;
    if (warp >= BATCHSZ) return;
    int it = idx[warp];
    float2 v  = reinterpret_cast<const float2*>(emb + (size_t)it * DIM)[lane];
    float2 ww = reinterpret_cast<const float2*>(w)[lane];
    float s = v.x * ww.x + v.y * ww.y;
    #pragma unroll
    for (int o = 16; o; o >>= 1) s += __shfl_xor_sync(0xFFFFFFFFu, s, o);
    if (lane == 0) out[warp] = 1.0f / (1.0f + __expf(-(s + bias[0])));
}

// ---------------- kernel 3: streaming SupCon --------------------------------
// 128 CTAs x 256 thr. CTA owns 64 rows; loops 64 col-tiles of 128.
// smem: sB double-buffer 2x64KB ([k][col] splatted doubles), sA 16KB ([k][row]).
static __device__ __forceinline__ void prefetch_tile(double* sBbuf, int t, int tid) {
    #pragma unroll
    for (int c = tid; c < 4096; c += 256) {
        int k  = c >> 6;
        int co = (c & 63) << 1;
        unsigned dst = (unsigned)__cvta_generic_to_shared(sBbuf + k * 128 + co);
        const double* src = g_featd + (size_t)k * N_ITEMS + (size_t)t * 128 + co;
        asm volatile("cp.async.cg.shared.global [%0], [%1], 16;" :: "r"(dst), "l"(src));
    }
    asm volatile("cp.async.commit_group;" ::: "memory");
}

__global__ __launch_bounds__(256) void supcon_kernel(const int* __restrict__ labels) {
    extern __shared__ char dyn[];
    double* sB = reinterpret_cast<double*>(dyn);            // 2 * 64KB
    float*  sA = reinterpret_cast<float*>(dyn + 2 * 65536); // 16KB
    __shared__ float sred[8];

    const int tid = threadIdx.x;
    const int rg  = tid >> 5;     // warp id = row group (8 rows each)
    const int cg  = tid & 31;     // lane = col group
    const int R0  = blockIdx.x * 64;
    const int row0 = rg * 8;

    // A tile, transposed to [k][row]
    for (int i = tid; i < 64 * DIM; i += 256) {
        int row = i >> 6, k = i & 63;
        sA[k * 64 + row] = g_feat[(size_t)(R0) * DIM + i];
        (void)row;
    }
    prefetch_tile(sB, 0, tid);
    __syncthreads();

    // per-row: -max (== -s_ii/T), label
    float negM[8]; int rlab[8];
    #pragma unroll
    for (int r = 0; r < 8; r++) {
        float s = 0.f;
        #pragma unroll
        for (int k = 0; k < DIM; k++) { float a = sA[k * 64 + row0 + r]; s = fmaf(a, a, s); }
        negM[r] = -s * INV_T;
        rlab[r] = labels[R0 + row0 + r];
    }
    unsigned long long negM2[4];
    #pragma unroll
    for (int rp = 0; rp < 4; rp++) negM2[rp] = pack2(negM[2 * rp], negM[2 * rp + 1]);
    const unsigned long long invT2 = pack2(INV_T, INV_T);

    float Z[8], P[8], C[8];
    #pragma unroll
    for (int r = 0; r < 8; r++) { Z[r] = 0.f; P[r] = 0.f; C[r] = 0.f; }

    for (int t = 0; t < 64; t++) {
        asm volatile("cp.async.wait_group 0;" ::: "memory");
        __syncthreads();
        if (t + 1 < 64) prefetch_tile(sB + ((t + 1) & 1) * 8192, t + 1, tid);
        const double* B = sB + (t & 1) * 8192;

        unsigned long long acc[4][4];
        #pragma unroll
        for (int rp = 0; rp < 4; rp++)
            #pragma unroll
            for (int c = 0; c < 4; c++) acc[rp][c] = 0ull;

        #pragma unroll 16
        for (int k = 0; k < DIM; k++) {
            const ulonglong2* aP = reinterpret_cast<const ulonglong2*>(sA + k * 64 + row0);
            ulonglong2 a01 = aP[0];   // rows r0,r0+1 | r0+2,r0+3
            ulonglong2 a23 = aP[1];   // rows r0+4..r0+7
            const double* bP = B + k * 128 + cg;
            unsigned long long b0 = __double_as_longlong(bP[0]);
            unsigned long long b1 = __double_as_longlong(bP[32]);
            unsigned long long b2 = __double_as_longlong(bP[64]);
            unsigned long long b3 = __double_as_longlong(bP[96]);
            acc[0][0] = fma2(a01.x, b0, acc[0][0]);
            acc[1][0] = fma2(a01.y, b0, acc[1][0]);
            acc[2][0] = fma2(a23.x, b0, acc[2][0]);
            acc[3][0] = fma2(a23.y, b0, acc[3][0]);
            acc[0][1] = fma2(a01.x, b1, acc[0][1]);
            acc[1][1] = fma2(a01.y, b1, acc[1][1]);
            acc[2][1] = fma2(a23.x, b1, acc[2][1]);
            acc[3][1] = fma2(a23.y, b1, acc[3][1]);
            acc[0][2] = fma2(a01.x, b2, acc[0][2]);
            acc[1][2] = fma2(a01.y, b2, acc[1][2]);
            acc[2][2] = fma2(a23.x, b2, acc[2][2]);
            acc[3][2] = fma2(a23.y, b2, acc[3][2]);
            acc[0][3] = fma2(a01.x, b3, acc[0][3]);
            acc[1][3] = fma2(a01.y, b3, acc[1][3]);
            acc[2][3] = fma2(a23.x, b3, acc[2][3]);
            acc[3][3] = fma2(a23.y, b3, acc[3][3]);
        }

        // epilogue: logits = s/T - s_ii/T ; accumulate Z, P, count
        int jbase = t * 128 + cg;
        #pragma unroll
        for (int c = 0; c < 4; c++) {
            int j  = jbase + 32 * c;
            int jl = __ldg(&labels[j]);
            #pragma unroll
            for (int rp = 0; rp < 4; rp++) {
                unsigned long long l2 = fma2(acc[rp][c], invT2, negM2[rp]);
                float lo, hi;
                unpack2(l2, lo, hi);
                int i0 = R0 + row0 + 2 * rp;
                int i1 = i0 + 1;
                float elo = __expf(lo), ehi = __expf(hi);
                if (j != i0) {
                    Z[2 * rp] += elo;
                    if (jl == rlab[2 * rp])     { P[2 * rp]     += lo; C[2 * rp]     += 1.0f; }
                }
                if (j != i1) {
                    Z[2 * rp + 1] += ehi;
                    if (jl == rlab[2 * rp + 1]) { P[2 * rp + 1] += hi; C[2 * rp + 1] += 1.0f; }
                }
            }
        }
    }

    // reduce across the 32 lanes (each warp owns the same 8 rows)
    float wsum = 0.f;
    #pragma unroll
    for (int r = 0; r < 8; r++) {
        float z = Z[r], p = P[r], c = C[r];
        #pragma unroll
        for (int o = 16; o; o >>= 1) {
            z += __shfl_xor_sync(0xFFFFFFFFu, z, o);
            p += __shfl_xor_sync(0xFFFFFFFFu, p, o);
            c += __shfl_xor_sync(0xFFFFFFFFu, c, o);
        }
        if (cg == 0) wsum += (p - c * __logf(z + 1e-6f)) / (c + 1e-6f);
    }
    if (cg == 0) sred[rg] = wsum;
    __syncthreads();
    if (tid == 0) {
        float s = 0.f;
        #pragma unroll
        for (int i = 0; i < 8; i++) s += sred[i];
        g_partial[blockIdx.x] = s;
    }
}

// ---------------- kernel 4: finalize loss ---------------------------------
__global__ void finalize_kernel(float* __restrict__ out, int out_size) {
    __shared__ float s[128];
    s[threadIdx.x] = g_partial[threadIdx.x];
    __syncthreads();
    for (int o = 64; o; o >>= 1) {
        if (threadIdx.x < o) s[threadIdx.x] += s[threadIdx.x + o];
        __syncthreads();
    }
    if (threadIdx.x == 0) {
        float loss = -(s[0] / (float)N_ITEMS);
        for (int i = BATCHSZ; i < out_size; i++) out[i] = loss;
    }
}

// ---------------- launch ----------------------------------------------------
extern "C" void kernel_launch(void* const* d_in, const int* in_sizes, int n_in,
                              void* d_out, int out_size) {
    const int*   idx    = (const int*)d_in[0];    // item_indices [4096]
    const int*   labels = (const int*)d_in[1];    // labels [8192]
    const float* emb    = (const float*)d_in[2];  // emb_weight [8192,64]
    const float* w      = (const float*)d_in[3];  // affine_w [64,1]
    const float* b      = (const float*)d_in[4];  // affine_b [1]
    float* out = (float*)d_out;                   // rating [4096] ++ supcon [1]

    const int SMEM = 2 * 65536 + 64 * 64 * 4;     // 147456 B
    cudaFuncSetAttribute(supcon_kernel, cudaFuncAttributeMaxDynamicSharedMemorySize, SMEM);

    normalize_kernel<<<N_ITEMS * 32 / 256, 256>>>(emb);
    rating_kernel<<<BATCHSZ * 32 / 256, 256>>>(idx, emb, w, b, out);
    supcon_kernel<<<128, 256, SMEM>>>(labels);
    finalize_kernel<<<1, 128>>>(out, out_size);
}

// round 3
// speedup vs baseline: 1.2920x; 1.2920x over previous
#include <cuda_runtime.h>
#include <cstdint>
#include <math.h>

#define N_ITEMS 8192
#define DIM     64
#define BATCHSZ 4096
#define INV_T   14.2857142857142857f   /* 1/0.07 */

// ---------------- device scratch (no allocations allowed) ----------------
__device__ float g_feat[N_ITEMS * DIM];            // normalized, [row][k]
__device__ float g_featT[DIM * N_ITEMS];           // normalized, [k][col]
__device__ float g_partial[128];

// ---------------- f32x2 helpers ------------------------------------------
static __device__ __forceinline__ unsigned long long fma2(unsigned long long a,
                                                          unsigned long long b,
                                                          unsigned long long c) {
    unsigned long long d;
    asm("fma.rn.f32x2 %0, %1, %2, %3;" : "=l"(d) : "l"(a), "l"(b), "l"(c));
    return d;
}
static __device__ __forceinline__ unsigned long long pack2(float lo, float hi) {
    unsigned long long d;
    asm("mov.b64 %0, {%1, %2};" : "=l"(d) : "f"(lo), "f"(hi));
    return d;
}
static __device__ __forceinline__ void unpack2(unsigned long long d, float& lo, float& hi) {
    asm("mov.b64 {%0, %1}, %2;" : "=f"(lo), "=f"(hi) : "l"(d));
}

// ---------------- kernel 1: row-normalize emb, write both layouts ---------
__global__ __launch_bounds__(256) void normalize_kernel(const float* __restrict__ emb) {
    int warp = (blockIdx.x * blockDim.x + threadIdx.x) >> 5;
    int lane = threadIdx.x & 31;
    if (warp >= N_ITEMS) return;
    float2 v = reinterpret_cast<const float2*>(emb + (size_t)warp * DIM)[lane];
    float ss = v.x * v.x + v.y * v.y;
    #pragma unroll
    for (int o = 16; o; o >>= 1) ss += __shfl_xor_sync(0xFFFFFFFFu, ss, o);
    float inv = 1.0f / fmaxf(sqrtf(ss), 1e-12f);
    float a = v.x * inv, b = v.y * inv;
    g_feat[warp * DIM + 2 * lane]     = a;
    g_feat[warp * DIM + 2 * lane + 1] = b;
    g_featT[(2 * lane)     * N_ITEMS + warp] = a;
    g_featT[(2 * lane + 1) * N_ITEMS + warp] = b;
}

// ---------------- kernel 2: rating = sigmoid(emb[idx] @ w + b) ------------
__global__ __launch_bounds__(256) void rating_kernel(const int* __restrict__ idx,
                                                     const float* __restrict__ emb,
                                                     const float* __restrict__ w,
                                                     const float* __restrict__ bias,
                                                     float* __restrict__ out) {
    int warp = (blockIdx.x * blockDim.x + threadIdx.x) >> 5;
    int lane = threadIdx.x & 31;
    if (warp >= BATCHSZ) return;
    int it = idx[warp];
    float2 v  = reinterpret_cast<const float2*>(emb + (size_t)it * DIM)[lane];
    float2 ww = reinterpret_cast<const float2*>(w)[lane];
    float s = v.x * ww.x + v.y * ww.y;
    #pragma unroll
    for (int o = 16; o; o >>= 1) s += __shfl_xor_sync(0xFFFFFFFFu, s, o);
    if (lane == 0) out[warp] = 1.0f / (1.0f + __expf(-(s + bias[0])));
}

// ---------------- kernel 3: streaming SupCon --------------------------------
// 128 CTAs x 256 thr. CTA owns 64 rows; 32 col-tiles of 256 columns.
// smem: sB double-buffer 2x64KB (plain floats [k][col]),
//       sA 32KB (splatted doubles [k][row], lo=hi=a).
// Per warp: 8 rows (broadcast A) x 16 cols (8 f32x2 col-pairs, 4 groups).
static __device__ __forceinline__ void prefetch_tile(float* dst, int t, int tid) {
    #pragma unroll
    for (int i = tid; i < 4096; i += 256) {
        int k = i >> 6;            // 0..63
        int c = (i & 63) << 2;     // 0..252
        unsigned d = (unsigned)__cvta_generic_to_shared(dst + k * 256 + c);
        const float* src = g_featT + (size_t)k * N_ITEMS + (size_t)t * 256 + c;
        asm volatile("cp.async.cg.shared.global [%0], [%1], 16;" :: "r"(d), "l"(src));
    }
    asm volatile("cp.async.commit_group;" ::: "memory");
}

__global__ __launch_bounds__(256) void supcon_kernel(const int* __restrict__ labels) {
    extern __shared__ char dyn[];
    float*  sB = reinterpret_cast<float*>(dyn);              // 2 * 64KB
    double* sA = reinterpret_cast<double*>(dyn + 2 * 65536); // 32KB
    __shared__ float sred[8];

    const int tid  = threadIdx.x;
    const int rg   = tid >> 5;     // warp id: owns rows rg*8 .. rg*8+7
    const int cg   = tid & 31;     // lane
    const int R0   = blockIdx.x * 64;
    const int row0 = rg * 8;

    // A tile: splatted doubles [k][row]
    for (int i = tid; i < 64 * DIM; i += 256) {
        int k = i >> 6, row = i & 63;
        float a = g_feat[(size_t)(R0 + row) * DIM + k];
        sA[k * 64 + row] = __longlong_as_double((long long)pack2(a, a));
    }
    prefetch_tile(sB, 0, tid);
    __syncthreads();

    // per-row: -max (== -s_ii/T, diagonal is the row max), label
    float negM[8]; int rlab[8];
    #pragma unroll
    for (int r = 0; r < 8; r++) {
        float s = 0.f;
        #pragma unroll
        for (int k = 0; k < DIM; k++) {
            float lo, hi;
            unpack2((unsigned long long)__double_as_longlong(sA[k * 64 + row0 + r]), lo, hi);
            s = fmaf(lo, lo, s);
            (void)hi;
        }
        negM[r] = -s * INV_T;
        rlab[r] = labels[R0 + row0 + r];
    }
    unsigned long long negM2[8];
    #pragma unroll
    for (int r = 0; r < 8; r++) negM2[r] = pack2(negM[r], negM[r]);
    const unsigned long long invT2 = pack2(INV_T, INV_T);

    float Z[8], P[8], C[8];
    #pragma unroll
    for (int r = 0; r < 8; r++) { Z[r] = 0.f; P[r] = 0.f; C[r] = 0.f; }

    for (int t = 0; t < 32; t++) {
        asm volatile("cp.async.wait_group 0;" ::: "memory");
        __syncthreads();
        if (t + 1 < 32) prefetch_tile(sB + ((t + 1) & 1) * 16384, t + 1, tid);
        const float* B = sB + (t & 1) * 16384;

        unsigned long long acc[8][4];
        #pragma unroll
        for (int r = 0; r < 8; r++)
            #pragma unroll
            for (int c = 0; c < 4; c++) acc[r][c] = 0ull;

        #pragma unroll 4
        for (int k = 0; k < DIM; k++) {
            // A: 8 splatted row values, broadcast loads (conflict-free)
            const ulonglong2* aP = reinterpret_cast<const ulonglong2*>(sA + k * 64 + row0);
            ulonglong2 a01 = aP[0];
            ulonglong2 a23 = aP[1];
            ulonglong2 a45 = aP[2];
            ulonglong2 a67 = aP[3];
            const float* Bk = B + k * 256 + 2 * cg;
            unsigned long long b0 = *reinterpret_cast<const unsigned long long*>(Bk);
            unsigned long long b1 = *reinterpret_cast<const unsigned long long*>(Bk + 64);
            unsigned long long b2 = *reinterpret_cast<const unsigned long long*>(Bk + 128);
            unsigned long long b3 = *reinterpret_cast<const unsigned long long*>(Bk + 192);
            #pragma unroll
            for (int c = 0; c < 4; c++) {
                unsigned long long b = (c == 0) ? b0 : (c == 1) ? b1 : (c == 2) ? b2 : b3;
                acc[0][c] = fma2(a01.x, b, acc[0][c]);
                acc[1][c] = fma2(a01.y, b, acc[1][c]);
                acc[2][c] = fma2(a23.x, b, acc[2][c]);
                acc[3][c] = fma2(a23.y, b, acc[3][c]);
                acc[4][c] = fma2(a45.x, b, acc[4][c]);
                acc[5][c] = fma2(a45.y, b, acc[5][c]);
                acc[6][c] = fma2(a67.x, b, acc[6][c]);
                acc[7][c] = fma2(a67.y, b, acc[7][c]);
            }
        }

        // epilogue: logits = s/T - s_ii/T ; accumulate Z, P, C
        #pragma unroll
        for (int c = 0; c < 4; c++) {
            int j  = t * 256 + 64 * c + 2 * cg;
            int2 jl = __ldg(reinterpret_cast<const int2*>(labels + j));
            #pragma unroll
            for (int r = 0; r < 8; r++) {
                int rr = R0 + row0 + r;
                unsigned long long l2 = fma2(acc[r][c], invT2, negM2[r]);
                float lo, hi; unpack2(l2, lo, hi);
                float elo = __expf(lo), ehi = __expf(hi);
                if (j != rr) {
                    Z[r] += elo;
                    if (jl.x == rlab[r]) { P[r] += lo; C[r] += 1.0f; }
                }
                if (j + 1 != rr) {
                    Z[r] += ehi;
                    if (jl.y == rlab[r]) { P[r] += hi; C[r] += 1.0f; }
                }
            }
        }
    }

    // lane-reduce each row's Z/P/C across the warp
    float wsum = 0.f;
    #pragma unroll
    for (int r = 0; r < 8; r++) {
        float z = Z[r], p = P[r], c = C[r];
        #pragma unroll
        for (int o = 16; o; o >>= 1) {
            z += __shfl_xor_sync(0xFFFFFFFFu, z, o);
            p += __shfl_xor_sync(0xFFFFFFFFu, p, o);
            c += __shfl_xor_sync(0xFFFFFFFFu, c, o);
        }
        if (cg == 0) wsum += (p - c * __logf(z + 1e-6f)) / (c + 1e-6f);
    }
    if (cg == 0) sred[rg] = wsum;
    __syncthreads();
    if (tid == 0) {
        float s = 0.f;
        #pragma unroll
        for (int i = 0; i < 8; i++) s += sred[i];
        g_partial[blockIdx.x] = s;
    }
}

// ---------------- kernel 4: finalize loss ---------------------------------
__global__ void finalize_kernel(float* __restrict__ out, int out_size) {
    __shared__ float s[128];
    s[threadIdx.x] = g_partial[threadIdx.x];
    __syncthreads();
    for (int o = 64; o; o >>= 1) {
        if (threadIdx.x < o) s[threadIdx.x] += s[threadIdx.x + o];
        __syncthreads();
    }
    if (threadIdx.x == 0) {
        float loss = -(s[0] / (float)N_ITEMS);
        for (int i = BATCHSZ; i < out_size; i++) out[i] = loss;
    }
}

// ---------------- launch ----------------------------------------------------
extern "C" void kernel_launch(void* const* d_in, const int* in_sizes, int n_in,
                              void* d_out, int out_size) {
    const int*   idx    = (const int*)d_in[0];    // item_indices [4096]
    const int*   labels = (const int*)d_in[1];    // labels [8192]
    const float* emb    = (const float*)d_in[2];  // emb_weight [8192,64]
    const float* w      = (const float*)d_in[3];  // affine_w [64,1]
    const float* b      = (const float*)d_in[4];  // affine_b [1]
    float* out = (float*)d_out;                   // rating [4096] ++ supcon [1]

    const int SMEM = 2 * 65536 + 32768;           // 163840 B
    cudaFuncSetAttribute(supcon_kernel, cudaFuncAttributeMaxDynamicSharedMemorySize, SMEM);

    normalize_kernel<<<N_ITEMS * 32 / 256, 256>>>(emb);
    rating_kernel<<<BATCHSZ * 32 / 256, 256>>>(idx, emb, w, b, out);
    supcon_kernel<<<128, 256, SMEM>>>(labels);
    finalize_kernel<<<1, 128>>>(out, out_size);
}

// round 5
// speedup vs baseline: 3.8686x; 2.9944x over previous
#include <cuda_runtime.h>
#include <cuda_bf16.h>
#include <cstdint>
#include <math.h>

#define N_ITEMS 8192
#define DIM     64
#define BATCHSZ 4096
#define LN2F    0.69314718055994531f
#define ITLG2E  20.609947181438156f   /* (1/0.07) * log2(e) */
#define NCH     32

// ---------------- device scratch (no allocations allowed) ----------------
__device__ uint32_t g_fh[N_ITEMS * 32];   // bf16x2 hi-split, [row][32]
__device__ uint32_t g_fl[N_ITEMS * 32];   // bf16x2 lo-split
__device__ float    g_sii[N_ITEMS];       // fp32 self-dot
__device__ float    g_Z[2 * N_ITEMS];
__device__ float    g_P[2 * N_ITEMS];     // log2-domain positive-logit sums
__device__ float    g_C[2 * N_ITEMS];

// ---------------- helpers --------------------------------------------------
static __device__ __forceinline__ uint32_t smem_u32(const void* p) {
    uint32_t a;
    asm("{ .reg .u64 t; cvta.to.shared.u64 t, %1; cvt.u32.u64 %0, t; }" : "=r"(a) : "l"(p));
    return a;
}
static __device__ __forceinline__ float ex2f(float x) {
    float y; asm("ex2.approx.ftz.f32 %0, %1;" : "=f"(y) : "f"(x)); return y;
}
static __device__ __forceinline__ void cp16(uint32_t dst, const void* src) {
    asm volatile("cp.async.cg.shared.global [%0], [%1], 16;" :: "r"(dst), "l"(src));
}
#define CP_COMMIT() asm volatile("cp.async.commit_group;" ::: "memory")
static __device__ __forceinline__ void ldsm4(uint32_t* r, uint32_t addr) {
    asm volatile("ldmatrix.sync.aligned.m8n8.x4.shared.b16 {%0,%1,%2,%3}, [%4];"
                 : "=r"(r[0]), "=r"(r[1]), "=r"(r[2]), "=r"(r[3]) : "r"(addr));
}
static __device__ __forceinline__ void ldsm2(uint32_t* r, uint32_t addr) {
    asm volatile("ldmatrix.sync.aligned.m8n8.x2.shared.b16 {%0,%1}, [%2];"
                 : "=r"(r[0]), "=r"(r[1]) : "r"(addr));
}
static __device__ __forceinline__ void mma16816(float* d, const uint32_t* a, const uint32_t* b) {
    asm volatile("mma.sync.aligned.m16n8k16.row.col.f32.bf16.bf16.f32 "
                 "{%0,%1,%2,%3}, {%4,%5,%6,%7}, {%8,%9}, {%0,%1,%2,%3};"
                 : "+f"(d[0]), "+f"(d[1]), "+f"(d[2]), "+f"(d[3])
                 : "r"(a[0]), "r"(a[1]), "r"(a[2]), "r"(a[3]), "r"(b[0]), "r"(b[1]));
}

// ---------------- kernel 1: normalize + bf16 hi/lo split ------------------
__global__ __launch_bounds__(256) void normalize_kernel(const float* __restrict__ emb) {
    int warp = (blockIdx.x * blockDim.x + threadIdx.x) >> 5;
    int lane = threadIdx.x & 31;
    if (warp >= N_ITEMS) return;
    float2 v = reinterpret_cast<const float2*>(emb + (size_t)warp * DIM)[lane];
    float ss = v.x * v.x + v.y * v.y;
    #pragma unroll
    for (int o = 16; o; o >>= 1) ss += __shfl_xor_sync(0xFFFFFFFFu, ss, o);
    float inv = 1.0f / fmaxf(sqrtf(ss), 1e-12f);
    float a = v.x * inv, b = v.y * inv;
    float sii = a * a + b * b;
    #pragma unroll
    for (int o = 16; o; o >>= 1) sii += __shfl_xor_sync(0xFFFFFFFFu, sii, o);
    __nv_bfloat16 ah = __float2bfloat16(a), bh = __float2bfloat16(b);
    float al = a - __bfloat162float(ah), bl = b - __bfloat162float(bh);
    __nv_bfloat16 alb = __float2bfloat16(al), blb = __float2bfloat16(bl);
    g_fh[warp * 32 + lane] = (uint32_t)__bfloat16_as_ushort(ah) |
                             ((uint32_t)__bfloat16_as_ushort(bh) << 16);
    g_fl[warp * 32 + lane] = (uint32_t)__bfloat16_as_ushort(alb) |
                             ((uint32_t)__bfloat16_as_ushort(blb) << 16);
    if (lane == 0) g_sii[warp] = sii;
}

// ---------------- kernel 2: rating ----------------------------------------
__global__ __launch_bounds__(256) void rating_kernel(const int* __restrict__ idx,
                                                     const float* __restrict__ emb,
                                                     const float* __restrict__ w,
                                                     const float* __restrict__ bias,
                                                     float* __restrict__ out) {
    int warp = (blockIdx.x * blockDim.x + threadIdx.x) >> 5;
    int lane = threadIdx.x & 31;
    if (warp >= BATCHSZ) return;
    int it = idx[warp];
    float2 v  = reinterpret_cast<const float2*>(emb + (size_t)it * DIM)[lane];
    float2 ww = reinterpret_cast<const float2*>(w)[lane];
    float s = v.x * ww.x + v.y * ww.y;
    #pragma unroll
    for (int o = 16; o; o >>= 1) s += __shfl_xor_sync(0xFFFFFFFFu, s, o);
    if (lane == 0) out[warp] = 1.0f / (1.0f + __expf(-(s + bias[0])));
}

// ---------------- kernel 3: HMMA SupCon ------------------------------------
// grid (64,2), 256 thr. CTA: 128 rows x 4096 cols, 32 chunks of 128 cols.
// smem: Ah[0,16K) Al[16K,32K), B ring 4 x {Bh 16K, Bl 16K} at 32K.
// Swizzle: 16B chunk c of row r stored at c ^ (r&7). Warp w: rows w*16..+15.
static __device__ __forceinline__ void load_128x128(uint32_t sdst, const char* gsrc, int tid) {
    #pragma unroll
    for (int i = tid; i < 1024; i += 256) {
        uint32_t off = ((i >> 3) * 128) + ((i & 7) * 16);
        uint32_t sw  = off ^ ((off >> 3) & 0x70);
        cp16(sdst + sw, gsrc + off);
    }
}

__global__ __launch_bounds__(256, 1) void supcon_kernel(const int* __restrict__ labels) {
    extern __shared__ char dyn[];
    __shared__ int sLab[4][128];

    const int tid  = threadIdx.x;
    const int w    = tid >> 5;
    const int lane = tid & 31;
    const int R0   = blockIdx.x * 128;
    const int C0   = blockIdx.y * 4096;
    const uint32_t sbase = smem_u32(dyn);
    const uint32_t slabA = smem_u32(&sLab[0][0]);

    // ---- prologue: A tiles + chunks 0..3 (4 commit groups) ----
    load_128x128(sbase,         (const char*)g_fh + (size_t)R0 * 128, tid);
    load_128x128(sbase + 16384, (const char*)g_fl + (size_t)R0 * 128, tid);
    #pragma unroll
    for (int pf = 0; pf < 4; pf++) {
        uint32_t bd = sbase + 32768 + (uint32_t)pf * 32768;
        load_128x128(bd,         (const char*)g_fh + (size_t)(C0 + pf * 128) * 128, tid);
        load_128x128(bd + 16384, (const char*)g_fl + (size_t)(C0 + pf * 128) * 128, tid);
        if (tid < 32) cp16(slabA + pf * 512 + tid * 16,
                           (const char*)(labels + C0 + pf * 128) + tid * 16);
        CP_COMMIT();
    }
    asm volatile("cp.async.wait_group 3;" ::: "memory");
    __syncthreads();

    // ---- A fragments (chunk-invariant): rows w*16..w*16+15, K=64 ----
    uint32_t ah[4][4], al[4][4];
    {
        int arow = w * 16 + (lane & 15);
        uint32_t rbase = sbase + (uint32_t)arow * 128;
        #pragma unroll
        for (int ks = 0; ks < 4; ks++) {
            uint32_t c = (uint32_t)(ks * 2 + (lane >> 4));
            uint32_t a = rbase + ((c ^ (arow & 7)) << 4);
            ldsm4(ah[ks], a);
            ldsm4(al[ks], a + 16384);
        }
    }

    // per-thread row constants (rows grow0 = w*16 + lane/4, grow1 = +8)
    const int grow0 = R0 + w * 16 + (lane >> 2);
    const int grow1 = grow0 + 8;
    const float negM0 = -g_sii[grow0] * ITLG2E;
    const float negM1 = -g_sii[grow1] * ITLG2E;
    const int rlab0 = labels[grow0];
    const int rlab1 = labels[grow1];
    float Z0 = 0.f, P0 = 0.f, C0c = 0.f, Z1 = 0.f, P1 = 0.f, C1c = 0.f;

    const int brow = lane & 7;                  // B-tile row (n within 8)
    const uint32_t bksel = (uint32_t)((lane >> 3) & 1);

    for (int t = 0; t < NCH; t++) {
        if (t > 0) {
            asm volatile("cp.async.wait_group 3;" ::: "memory");
            __syncthreads();
        }
        const int buf = t & 3;
        const uint32_t Bb = sbase + 32768 + (uint32_t)buf * 32768;

        float acc[16][4];
        #pragma unroll
        for (int nt = 0; nt < 16; nt++)
            #pragma unroll
            for (int i = 0; i < 4; i++) acc[nt][i] = 0.f;

        #pragma unroll
        for (int nt = 0; nt < 16; nt++) {
            int n = nt * 8 + brow;
            uint32_t nb = Bb + (uint32_t)n * 128;
            uint32_t bh[4][2], bl[4][2];
            #pragma unroll
            for (int ks = 0; ks < 4; ks++) {
                uint32_t c = (uint32_t)(ks * 2) + bksel;
                uint32_t a = nb + ((c ^ (n & 7)) << 4);
                ldsm2(bh[ks], a);
                ldsm2(bl[ks], a + 16384);
            }
            #pragma unroll
            for (int ks = 0; ks < 4; ks++) {
                mma16816(acc[nt], ah[ks], bh[ks]);
                mma16816(acc[nt], ah[ks], bl[ks]);
                mma16816(acc[nt], al[ks], bh[ks]);
            }
        }

        // ---- epilogue: thread owns rows grow0/grow1, cols nt*8 + 2*(lane&3) ----
        const int jb = C0 + t * 128 + 2 * (lane & 3);
        const int lb = 2 * (lane & 3);
        #pragma unroll
        for (int nt = 0; nt < 16; nt++) {
            int jc  = jb + nt * 8;
            int jl0 = sLab[buf][lb + nt * 8];
            int jl1 = sLab[buf][lb + nt * 8 + 1];
            {
                float l2 = fmaf(acc[nt][0], ITLG2E, negM0);
                float e  = ex2f(l2);
                if (jc != grow0)     { Z0 += e; if (jl0 == rlab0) { P0 += l2; C0c += 1.f; } }
            }
            {
                float l2 = fmaf(acc[nt][1], ITLG2E, negM0);
                float e  = ex2f(l2);
                if (jc + 1 != grow0) { Z0 += e; if (jl1 == rlab0) { P0 += l2; C0c += 1.f; } }
            }
            {
                float l2 = fmaf(acc[nt][2], ITLG2E, negM1);
                float e  = ex2f(l2);
                if (jc != grow1)     { Z1 += e; if (jl0 == rlab1) { P1 += l2; C1c += 1.f; } }
            }
            {
                float l2 = fmaf(acc[nt][3], ITLG2E, negM1);
                float e  = ex2f(l2);
                if (jc + 1 != grow1) { Z1 += e; if (jl1 == rlab1) { P1 += l2; C1c += 1.f; } }
            }
        }

        __syncthreads();   // everyone done with buf t & its labels
        // prefetch chunk (t+4) (wraps; redundant tail loads are harmless)
        {
            int pc = (t + 4) & 31;
            load_128x128(Bb,         (const char*)g_fh + (size_t)(C0 + pc * 128) * 128, tid);
            load_128x128(Bb + 16384, (const char*)g_fl + (size_t)(C0 + pc * 128) * 128, tid);
            if (tid < 32) cp16(slabA + buf * 512 + tid * 16,
                               (const char*)(labels + C0 + pc * 128) + tid * 16);
            CP_COMMIT();
        }
    }

    // reduce across the quad (lanes sharing a row differ in lane&3)
    #pragma unroll
    for (int o = 1; o <= 2; o <<= 1) {
        Z0 += __shfl_xor_sync(0xFFFFFFFFu, Z0, o);
        P0 += __shfl_xor_sync(0xFFFFFFFFu, P0, o);
        C0c += __shfl_xor_sync(0xFFFFFFFFu, C0c, o);
        Z1 += __shfl_xor_sync(0xFFFFFFFFu, Z1, o);
        P1 += __shfl_xor_sync(0xFFFFFFFFu, P1, o);
        C1c += __shfl_xor_sync(0xFFFFFFFFu, C1c, o);
    }
    if ((lane & 3) == 0) {
        int gi = blockIdx.y * N_ITEMS + grow0;
        g_Z[gi] = Z0; g_P[gi] = P0; g_C[gi] = C0c;
        g_Z[gi + 8] = Z1; g_P[gi + 8] = P1; g_C[gi + 8] = C1c;
    }
}

// ---------------- kernel 4: finalize loss ---------------------------------
__global__ __launch_bounds__(1024) void finalize_kernel(float* __restrict__ out, int out_size) {
    __shared__ float s[1024];
    int tid = threadIdx.x;
    float acc = 0.f;
    #pragma unroll
    for (int k = 0; k < 8; k++) {
        int r = tid + k * 1024;
        float Zv = g_Z[r] + g_Z[N_ITEMS + r];
        float Pv = (g_P[r] + g_P[N_ITEMS + r]) * LN2F;
        float Cv = g_C[r] + g_C[N_ITEMS + r];
        acc += (Pv - Cv * logf(Zv + 1e-6f)) / (Cv + 1e-6f);
    }
    s[tid] = acc;
    __syncthreads();
    for (int o = 512; o; o >>= 1) {
        if (tid < o) s[tid] += s[tid + o];
        __syncthreads();
    }
    if (tid == 0) {
        float loss = -(s[0] / (float)N_ITEMS);
        for (int i = BATCHSZ; i < out_size; i++) out[i] = loss;
    }
}

// ---------------- launch ----------------------------------------------------
extern "C" void kernel_launch(void* const* d_in, const int* in_sizes, int n_in,
                              void* d_out, int out_size) {
    const int*   idx    = (const int*)d_in[0];
    const int*   labels = (const int*)d_in[1];
    const float* emb    = (const float*)d_in[2];
    const float* w      = (const float*)d_in[3];
    const float* b      = (const float*)d_in[4];
    float* out = (float*)d_out;

    const int SMEM = 32768 + 4 * 32768;   // 163840
    cudaFuncSetAttribute(supcon_kernel, cudaFuncAttributeMaxDynamicSharedMemorySize, SMEM);

    normalize_kernel<<<N_ITEMS * 32 / 256, 256>>>(emb);
    rating_kernel<<<BATCHSZ * 32 / 256, 256>>>(idx, emb, w, b, out);
    supcon_kernel<<<dim3(64, 2, 1), 256, SMEM>>>(labels);
    finalize_kernel<<<1, 1024>>>(out, out_size);
}